// round 1
// baseline (speedup 1.0000x reference)
#include <cuda_runtime.h>
#include <cuda_bf16.h>

#define CROP 81
#define PIX (CROP * CROP)   // 6561

// One thread per output grid point (n, p, i, j).
// idx = ((n*6 + p)*81 + i)*81 + j  -> exactly the flattened croped_pred index.
__global__ __launch_bounds__(256)
void selectnet_kernel(const float* __restrict__ img,
                      const int*   __restrict__ label,
                      const float* __restrict__ points,
                      float*       __restrict__ out,
                      int N, int H, int W)
{
    const int TOT = N * 6 * PIX;
    int idx = blockIdx.x * blockDim.x + threadIdx.x;
    if (idx >= TOT) return;

    int j = idx % CROP;
    int i = (idx / CROP) % CROP;
    int q = idx / PIX;          // n*6 + p
    int p = q % 6;
    int n = q / 6;

    // points: (N, 9, 2); [k][0] = py, [k][1] = px
    const float* pt = points + (size_t)n * 18;
    float py, px;
    if (p < 5) {
        py = pt[(p + 1) * 2 + 0];
        px = pt[(p + 1) * 2 + 1];
    } else {
        // mean of points 6..8 : ((a+b)+c)/3, IEEE divide
        py = __fdiv_rn(__fadd_rn(__fadd_rn(pt[12], pt[14]), pt[16]), 3.0f);
        px = __fdiv_rn(__fadd_rn(__fadd_rn(pt[13], pt[15]), pt[17]), 3.0f);
    }

    const float fw = (float)(W - 1);          // 511
    const float fh = (float)(H - 1);          // 511
    const float sx = (float)(80.0 / 511.0);   // (CROP-1)/(W-1), f64->f32 like python weak scalar
    const float sy = (float)(80.0 / 512.0);   // (CROP-1)/H  (NOTE: H, not H-1 — reference asymmetry)
    const float delta = __fdiv_rn(2.0f, 80.0f); // jnp.linspace step

    // tx = -1 + 2*px/(W-1)  — separate-rounded ops, no FMA contraction
    float tx = __fadd_rn(-1.0f, __fdiv_rn(__fmul_rn(2.0f, px), fw));
    float ty = __fadd_rn(-1.0f, __fdiv_rn(__fmul_rn(2.0f, py), fh));

    // base[j] = -1 + j*delta  (linspace)
    float basej = __fadd_rn(-1.0f, __fmul_rn((float)j, delta));
    float basei = __fadd_rn(-1.0f, __fmul_rn((float)i, delta));

    float gx = __fadd_rn(__fmul_rn(sx, basej), tx);
    float gy = __fadd_rn(__fmul_rn(sy, basei), ty);

    // ix = ((gx + 1) * 0.5) * (W-1)
    float ix = __fmul_rn(__fmul_rn(__fadd_rn(gx, 1.0f), 0.5f), fw);
    float iy = __fmul_rn(__fmul_rn(__fadd_rn(gy, 1.0f), 0.5f), fh);

    // ---------------- bilinear sample of img ----------------
    float x0f = floorf(ix), y0f = floorf(iy);
    float wx1 = ix - x0f,   wy1 = iy - y0f;
    float wx0 = 1.0f - wx1, wy0 = 1.0f - wy1;

    int x0 = (int)x0f, y0 = (int)y0f;
    int x1 = x0 + 1,   y1 = y0 + 1;

    bool vx0 = (x0 >= 0) && (x0 <= W - 1);
    bool vx1 = (x1 >= 0) && (x1 <= W - 1);
    bool vy0 = (y0 >= 0) && (y0 <= H - 1);
    bool vy1 = (y1 >= 0) && (y1 <= H - 1);

    // zeroing the weight == reference's (vals * valid) * weight
    float w00 = (vx0 && vy0) ? wx0 * wy0 : 0.0f;
    float w10 = (vx1 && vy0) ? wx1 * wy0 : 0.0f;
    float w01 = (vx0 && vy1) ? wx0 * wy1 : 0.0f;
    float w11 = (vx1 && vy1) ? wx1 * wy1 : 0.0f;

    int cx0 = min(max(x0, 0), W - 1);
    int cx1 = min(max(x1, 0), W - 1);
    int cy0 = min(max(y0, 0), H - 1);
    int cy1 = min(max(y1, 0), H - 1);

    const size_t plane = (size_t)H * W;
    const float* imgn = img + (size_t)n * 3 * plane;
    int row0 = cy0 * W, row1 = cy1 * W;

    int r = i * CROP + j;
    size_t obase = (size_t)q * (3 * PIX) + r;

    #pragma unroll
    for (int c = 0; c < 3; ++c) {
        const float* ip = imgn + (size_t)c * plane;
        float v00 = __ldg(ip + row0 + cx0);
        float v10 = __ldg(ip + row0 + cx1);
        float v01 = __ldg(ip + row1 + cx0);
        float v11 = __ldg(ip + row1 + cx1);
        out[obase + (size_t)c * PIX] = v00 * w00 + v10 * w10 + v01 * w01 + v11 * w11;
    }

    // ---------------- nearest-sampled label -> pred ----------------
    float xr = rintf(ix);   // round-half-to-even == jnp.round
    float yr = rintf(iy);
    bool lv = (xr >= 0.0f) && (xr <= fw) && (yr >= 0.0f) && (yr <= fh);
    int lx = min(max((int)xr, 0), W - 1);
    int ly = min(max((int)yr, 0), H - 1);

    int lab = 0;
    if (lv) lab = __ldg(label + (size_t)n * plane + (size_t)ly * W + lx);

    float pred;
    if (p < 5) {
        pred = (lab == p + 1) ? 1.0f : 0.0f;
    } else {
        pred = (lab == 6) ? 1.0f : (lab == 7) ? 2.0f : (lab == 8) ? 3.0f : 0.0f;
    }
    out[(size_t)N * 6 * 3 * PIX + (size_t)idx] = pred;
}

extern "C" void kernel_launch(void* const* d_in, const int* in_sizes, int n_in,
                              void* d_out, int out_size) {
    const float* img    = (const float*)d_in[0];   // (N, 3, 512, 512) f32
    const int*   label  = (const int*)  d_in[1];   // (N, 512, 512) i32
    const float* points = (const float*)d_in[2];   // (N, 9, 2) f32
    float* out = (float*)d_out;

    int N = in_sizes[2] / 18;                      // points = N*9*2
    const int H = 512, W = 512;

    int tot = N * 6 * PIX;
    int threads = 256;
    int blocks = (tot + threads - 1) / threads;
    selectnet_kernel<<<blocks, threads>>>(img, label, points, out, N, H, W);
}

// round 2
// speedup vs baseline: 1.3936x; 1.3936x over previous
#include <cuda_runtime.h>
#include <cuda_bf16.h>

#define CROP 81
#define PIX  (CROP * CROP)        // 6561
#define SPLIT 4                   // row-chunks per crop
#define ROWS_PER ((CROP + SPLIT - 1) / SPLIT)   // 21

// One block = one (n,p) crop row-chunk. Per-crop separable tables in smem.
__global__ __launch_bounds__(256)
void selectnet_kernel(const float* __restrict__ img,
                      const int*   __restrict__ label,
                      const float* __restrict__ points,
                      float*       __restrict__ out,
                      int N)
{
    const int W = 512, H = 512;
    const size_t plane = (size_t)H * W;

    __shared__ float swx0[CROP], swx1[CROP];   // x weights (validity folded: 0 if invalid)
    __shared__ float swy0[CROP], swy1[CROP];   // y weights
    __shared__ int   sox0[CROP], sox1[CROP];   // clamped x offsets
    __shared__ int   soy0[CROP], soy1[CROP];   // clamped y*W offsets
    __shared__ int   slx[CROP],  sly[CROP];    // nearest label offsets, -1 = invalid

    const int q = blockIdx.x;       // n*6 + p
    const int p = q % 6;
    const int n = q / 6;
    const int t = threadIdx.x;

    if (t < CROP) {
        // ---- exact replication of reference float32 op chain ----
        const float* pt = points + (size_t)n * 18;
        float py, px;
        if (p < 5) {
            py = pt[(p + 1) * 2 + 0];
            px = pt[(p + 1) * 2 + 1];
        } else {
            py = __fdiv_rn(__fadd_rn(__fadd_rn(pt[12], pt[14]), pt[16]), 3.0f);
            px = __fdiv_rn(__fadd_rn(__fadd_rn(pt[13], pt[15]), pt[17]), 3.0f);
        }
        const float fw = 511.0f, fh = 511.0f;
        const float sx = (float)(80.0 / 511.0);   // (CROP-1)/(W-1)
        const float sy = (float)(80.0 / 512.0);   // (CROP-1)/H  (reference asymmetry)
        const float delta = __fdiv_rn(2.0f, 80.0f);

        float tx = __fadd_rn(-1.0f, __fdiv_rn(__fmul_rn(2.0f, px), fw));
        float ty = __fadd_rn(-1.0f, __fdiv_rn(__fmul_rn(2.0f, py), fh));
        float base = __fadd_rn(-1.0f, __fmul_rn((float)t, delta));
        float gx = __fadd_rn(__fmul_rn(sx, base), tx);
        float gy = __fadd_rn(__fmul_rn(sy, base), ty);
        float ix = __fmul_rn(__fmul_rn(__fadd_rn(gx, 1.0f), 0.5f), fw);
        float iy = __fmul_rn(__fmul_rn(__fadd_rn(gy, 1.0f), 0.5f), fh);

        // x tables (index = j)
        float x0f = floorf(ix);
        float wx1v = ix - x0f;
        int x0 = (int)x0f, x1 = x0 + 1;
        swx0[t] = (x0 >= 0 && x0 <= W - 1) ? (1.0f - wx1v) : 0.0f;
        swx1[t] = (x1 >= 0 && x1 <= W - 1) ? wx1v : 0.0f;
        sox0[t] = min(max(x0, 0), W - 1);
        sox1[t] = min(max(x1, 0), W - 1);
        float xr = rintf(ix);
        slx[t] = (xr >= 0.0f && xr <= fw) ? (int)xr : -1;

        // y tables (index = i)
        float y0f = floorf(iy);
        float wy1v = iy - y0f;
        int y0 = (int)y0f, y1 = y0 + 1;
        swy0[t] = (y0 >= 0 && y0 <= H - 1) ? (1.0f - wy1v) : 0.0f;
        swy1[t] = (y1 >= 0 && y1 <= H - 1) ? wy1v : 0.0f;
        soy0[t] = min(max(y0, 0), H - 1) * W;
        soy1[t] = min(max(y1, 0), H - 1) * W;
        float yr = rintf(iy);
        sly[t] = (yr >= 0.0f && yr <= fh) ? ((int)yr) * W : -1;
    }
    __syncthreads();

    const int rlo = blockIdx.y * ROWS_PER;
    const int rhi = min(rlo + ROWS_PER, CROP);
    const int npix = (rhi - rlo) * CROP;

    const float* imgn  = img   + (size_t)n * 3 * plane;
    const int*   labn  = label + (size_t)n * plane;
    float*       outq  = out   + (size_t)q * 3 * PIX;
    float*       predq = out   + (size_t)N * 6 * 3 * PIX + (size_t)q * PIX;
    const int target = p + 1;

    for (int r = t; r < npix; r += 256) {
        int i = rlo + r / CROP;
        int j = r % CROP;
        int pix = i * CROP + j;

        float a0 = swx0[j], a1 = swx1[j];
        float b0 = swy0[i], b1 = swy1[i];
        float w00 = a0 * b0, w10 = a1 * b0, w01 = a0 * b1, w11 = a1 * b1;

        int c0 = sox0[j], c1 = sox1[j];
        const float* p0 = imgn + soy0[i];
        const float* p1 = imgn + soy1[i];

        #pragma unroll
        for (int c = 0; c < 3; ++c) {
            float v00 = __ldg(p0 + (size_t)c * plane + c0);
            float v10 = __ldg(p0 + (size_t)c * plane + c1);
            float v01 = __ldg(p1 + (size_t)c * plane + c0);
            float v11 = __ldg(p1 + (size_t)c * plane + c1);
            outq[(size_t)c * PIX + pix] = v00 * w00 + v10 * w10 + v01 * w01 + v11 * w11;
        }

        int lx = slx[j], ly = sly[i];
        int lab = ((lx | ly) >= 0) ? __ldg(labn + ly + lx) : 0;
        float pred;
        if (p < 5) {
            pred = (lab == target) ? 1.0f : 0.0f;
        } else {
            pred = (lab == 6) ? 1.0f : (lab == 7) ? 2.0f : (lab == 8) ? 3.0f : 0.0f;
        }
        predq[pix] = pred;
    }
}

extern "C" void kernel_launch(void* const* d_in, const int* in_sizes, int n_in,
                              void* d_out, int out_size) {
    const float* img    = (const float*)d_in[0];   // (N, 3, 512, 512) f32
    const int*   label  = (const int*)  d_in[1];   // (N, 512, 512) i32
    const float* points = (const float*)d_in[2];   // (N, 9, 2) f32
    float* out = (float*)d_out;

    int N = in_sizes[2] / 18;                      // points = N*9*2

    dim3 grid(N * 6, SPLIT);
    selectnet_kernel<<<grid, 256>>>(img, label, points, out, N);
}

// round 3
// speedup vs baseline: 1.5113x; 1.0845x over previous
#include <cuda_runtime.h>
#include <cuda_bf16.h>

#define CROP 81
#define PIX  (CROP * CROP)        // 6561
#define SPLIT 4                   // row-chunks per crop
#define ROWS_PER ((CROP + SPLIT - 1) / SPLIT)   // 21
#define THREADS 256

// One block = one (n,p) crop row-chunk. Per-crop separable tables in smem.
// Each thread processes 2 pixels per iteration with batched loads (MLP x2).
__global__ __launch_bounds__(THREADS)
void selectnet_kernel(const float* __restrict__ img,
                      const int*   __restrict__ label,
                      const float* __restrict__ points,
                      float*       __restrict__ out,
                      int N)
{
    const int W = 512, H = 512;
    const size_t plane = (size_t)H * W;

    __shared__ float swx0[CROP], swx1[CROP];   // x weights (validity folded: 0 if invalid)
    __shared__ float swy0[CROP], swy1[CROP];   // y weights
    __shared__ int   sox0[CROP], sox1[CROP];   // clamped x offsets
    __shared__ int   soy0[CROP], soy1[CROP];   // clamped y*W offsets
    __shared__ int   slx[CROP],  sly[CROP];    // nearest label offsets, -1 = invalid

    const int q = blockIdx.x;       // n*6 + p
    const int p = q % 6;
    const int n = q / 6;
    const int t = threadIdx.x;

    if (t < CROP) {
        // ---- exact replication of reference float32 op chain ----
        const float* pt = points + (size_t)n * 18;
        float py, px;
        if (p < 5) {
            py = pt[(p + 1) * 2 + 0];
            px = pt[(p + 1) * 2 + 1];
        } else {
            py = __fdiv_rn(__fadd_rn(__fadd_rn(pt[12], pt[14]), pt[16]), 3.0f);
            px = __fdiv_rn(__fadd_rn(__fadd_rn(pt[13], pt[15]), pt[17]), 3.0f);
        }
        const float fw = 511.0f, fh = 511.0f;
        const float sx = (float)(80.0 / 511.0);   // (CROP-1)/(W-1)
        const float sy = (float)(80.0 / 512.0);   // (CROP-1)/H  (reference asymmetry)
        const float delta = __fdiv_rn(2.0f, 80.0f);

        float tx = __fadd_rn(-1.0f, __fdiv_rn(__fmul_rn(2.0f, px), fw));
        float ty = __fadd_rn(-1.0f, __fdiv_rn(__fmul_rn(2.0f, py), fh));
        float base = __fadd_rn(-1.0f, __fmul_rn((float)t, delta));
        float gx = __fadd_rn(__fmul_rn(sx, base), tx);
        float gy = __fadd_rn(__fmul_rn(sy, base), ty);
        float ix = __fmul_rn(__fmul_rn(__fadd_rn(gx, 1.0f), 0.5f), fw);
        float iy = __fmul_rn(__fmul_rn(__fadd_rn(gy, 1.0f), 0.5f), fh);

        // x tables (index = j)
        float x0f = floorf(ix);
        float wx1v = ix - x0f;
        int x0 = (int)x0f, x1 = x0 + 1;
        swx0[t] = (x0 >= 0 && x0 <= W - 1) ? (1.0f - wx1v) : 0.0f;
        swx1[t] = (x1 >= 0 && x1 <= W - 1) ? wx1v : 0.0f;
        sox0[t] = min(max(x0, 0), W - 1);
        sox1[t] = min(max(x1, 0), W - 1);
        float xr = rintf(ix);
        slx[t] = (xr >= 0.0f && xr <= fw) ? (int)xr : -1;

        // y tables (index = i)
        float y0f = floorf(iy);
        float wy1v = iy - y0f;
        int y0 = (int)y0f, y1 = y0 + 1;
        swy0[t] = (y0 >= 0 && y0 <= H - 1) ? (1.0f - wy1v) : 0.0f;
        swy1[t] = (y1 >= 0 && y1 <= H - 1) ? wy1v : 0.0f;
        soy0[t] = min(max(y0, 0), H - 1) * W;
        soy1[t] = min(max(y1, 0), H - 1) * W;
        float yr = rintf(iy);
        sly[t] = (yr >= 0.0f && yr <= fh) ? ((int)yr) * W : -1;
    }
    __syncthreads();

    const int rlo = blockIdx.y * ROWS_PER;
    const int rhi = min(rlo + ROWS_PER, CROP);
    const int npix = (rhi - rlo) * CROP;
    const int pixbase = rlo * CROP;

    const float* imgn  = img   + (size_t)n * 3 * plane;
    const int*   labn  = label + (size_t)n * plane;
    float*       outq  = out   + (size_t)q * 3 * PIX;
    float*       predq = out   + (size_t)N * 6 * 3 * PIX + (size_t)q * PIX;
    const int target = p + 1;

    for (int r = t; r < npix; r += 2 * THREADS) {
        // ---- pixel A = r ; pixel B = r + THREADS (clamped, stores predicated) ----
        int rB_raw = r + THREADS;
        bool hasB = rB_raw < npix;
        int rB = hasB ? rB_raw : r;            // clamp to a valid pixel (loads stay in-bounds)

        int iA = (r  + pixbase) / CROP, jA = (r  + pixbase) % CROP;
        int iB = (rB + pixbase) / CROP, jB = (rB + pixbase) % CROP;

        // table reads (LDS)
        float a0A = swx0[jA], a1A = swx1[jA], b0A = swy0[iA], b1A = swy1[iA];
        float a0B = swx0[jB], a1B = swx1[jB], b0B = swy0[iB], b1B = swy1[iB];
        int c0A = sox0[jA], c1A = sox1[jA];
        int c0B = sox0[jB], c1B = sox1[jB];
        const float* p0A = imgn + soy0[iA];
        const float* p1A = imgn + soy1[iA];
        const float* p0B = imgn + soy0[iB];
        const float* p1B = imgn + soy1[iB];
        int lxA = slx[jA], lyA = sly[iA];
        int lxB = slx[jB], lyB = sly[iB];

        // ---- batched global loads: 24 img taps + 2 label taps in flight ----
        float v[24];
        #pragma unroll
        for (int c = 0; c < 3; ++c) {
            size_t cp = (size_t)c * plane;
            v[c*4+0]  = __ldg(p0A + cp + c0A);
            v[c*4+1]  = __ldg(p0A + cp + c1A);
            v[c*4+2]  = __ldg(p1A + cp + c0A);
            v[c*4+3]  = __ldg(p1A + cp + c1A);
            v[12+c*4+0] = __ldg(p0B + cp + c0B);
            v[12+c*4+1] = __ldg(p0B + cp + c1B);
            v[12+c*4+2] = __ldg(p1B + cp + c0B);
            v[12+c*4+3] = __ldg(p1B + cp + c1B);
        }
        int labA = ((lxA | lyA) >= 0) ? __ldg(labn + lyA + lxA) : 0;
        int labB = ((lxB | lyB) >= 0) ? __ldg(labn + lyB + lxB) : 0;

        // ---- compute & store A ----
        float w00A = a0A * b0A, w10A = a1A * b0A, w01A = a0A * b1A, w11A = a1A * b1A;
        float w00B = a0B * b0B, w10B = a1B * b0B, w01B = a0B * b1B, w11B = a1B * b1B;
        int pixA = r + pixbase;
        int pixB = rB + pixbase;

        #pragma unroll
        for (int c = 0; c < 3; ++c) {
            float oA = v[c*4+0]*w00A + v[c*4+1]*w10A + v[c*4+2]*w01A + v[c*4+3]*w11A;
            outq[(size_t)c * PIX + pixA] = oA;
        }
        float predA;
        if (p < 5) predA = (labA == target) ? 1.0f : 0.0f;
        else predA = (labA == 6) ? 1.0f : (labA == 7) ? 2.0f : (labA == 8) ? 3.0f : 0.0f;
        predq[pixA] = predA;

        if (hasB) {
            #pragma unroll
            for (int c = 0; c < 3; ++c) {
                float oB = v[12+c*4+0]*w00B + v[12+c*4+1]*w10B + v[12+c*4+2]*w01B + v[12+c*4+3]*w11B;
                outq[(size_t)c * PIX + pixB] = oB;
            }
            float predB;
            if (p < 5) predB = (labB == target) ? 1.0f : 0.0f;
            else predB = (labB == 6) ? 1.0f : (labB == 7) ? 2.0f : (labB == 8) ? 3.0f : 0.0f;
            predq[pixB] = predB;
        }
    }
}

extern "C" void kernel_launch(void* const* d_in, const int* in_sizes, int n_in,
                              void* d_out, int out_size) {
    const float* img    = (const float*)d_in[0];   // (N, 3, 512, 512) f32
    const int*   label  = (const int*)  d_in[1];   // (N, 512, 512) i32
    const float* points = (const float*)d_in[2];   // (N, 9, 2) f32
    float* out = (float*)d_out;

    int N = in_sizes[2] / 18;                      // points = N*9*2

    dim3 grid(N * 6, SPLIT);
    selectnet_kernel<<<grid, THREADS>>>(img, label, points, out, N);
}

// round 5
// speedup vs baseline: 1.6926x; 1.1199x over previous
#include <cuda_runtime.h>
#include <cuda_bf16.h>

#define CROP 81
#define PIX  (CROP * CROP)        // 6561
#define SPLIT 4                   // row-chunks per crop
#define ROWS_PER ((CROP + SPLIT - 1) / SPLIT)   // 21
#define THREADS 256

// One block = one (n,p) crop row-chunk. Packed separable tables in smem
// (one LDS.128 per axis per pixel). Two pixels per thread per iteration.
// x entry: (wx0, wx1, bits[c0 | c1<<9 | (lx+1)<<18], unused)
// y entry: (wy0, wy1, bits[y0c | y1c<<9],            bits[lyrow])
__global__ __launch_bounds__(THREADS)
void selectnet_kernel(const float* __restrict__ img,
                      const int*   __restrict__ label,
                      const float* __restrict__ points,
                      float*       __restrict__ out,
                      int N)
{
    const int W = 512, H = 512;
    const size_t plane = (size_t)H * W;

    __shared__ float4 sxt[CROP];
    __shared__ float4 syt[CROP];

    const int q = blockIdx.x;       // n*6 + p
    const int p = q % 6;
    const int n = q / 6;
    const int t = threadIdx.x;

    if (t < CROP) {
        // ---- exact replication of reference float32 op chain ----
        const float* pt = points + (size_t)n * 18;
        float py, px;
        if (p < 5) {
            py = pt[(p + 1) * 2 + 0];
            px = pt[(p + 1) * 2 + 1];
        } else {
            py = __fdiv_rn(__fadd_rn(__fadd_rn(pt[12], pt[14]), pt[16]), 3.0f);
            px = __fdiv_rn(__fadd_rn(__fadd_rn(pt[13], pt[15]), pt[17]), 3.0f);
        }
        const float fw = 511.0f, fh = 511.0f;
        const float sx = (float)(80.0 / 511.0);   // (CROP-1)/(W-1)
        const float sy = (float)(80.0 / 512.0);   // (CROP-1)/H  (reference asymmetry)
        const float delta = __fdiv_rn(2.0f, 80.0f);

        float tx = __fadd_rn(-1.0f, __fdiv_rn(__fmul_rn(2.0f, px), fw));
        float ty = __fadd_rn(-1.0f, __fdiv_rn(__fmul_rn(2.0f, py), fh));
        float base = __fadd_rn(-1.0f, __fmul_rn((float)t, delta));
        float gx = __fadd_rn(__fmul_rn(sx, base), tx);
        float gy = __fadd_rn(__fmul_rn(sy, base), ty);
        float ix = __fmul_rn(__fmul_rn(__fadd_rn(gx, 1.0f), 0.5f), fw);
        float iy = __fmul_rn(__fmul_rn(__fadd_rn(gy, 1.0f), 0.5f), fh);

        // x table (index = j)
        float x0f = floorf(ix);
        float wx1v = ix - x0f;
        int x0 = (int)x0f, x1 = x0 + 1;
        float wx0 = (x0 >= 0 && x0 <= W - 1) ? (1.0f - wx1v) : 0.0f;
        float wx1 = (x1 >= 0 && x1 <= W - 1) ? wx1v : 0.0f;
        int c0 = min(max(x0, 0), W - 1);        // reference clip of x0
        int c1 = min(max(x1, 0), W - 1);        // reference clip of x1  (edge-correct)
        float xr = rintf(ix);
        int lx = (xr >= 0.0f && xr <= fw) ? (int)xr : -1;
        int xpack = c0 | (c1 << 9) | ((lx + 1) << 18);
        sxt[t] = make_float4(wx0, wx1, __int_as_float(xpack), 0.0f);

        // y table (index = i)
        float y0f = floorf(iy);
        float wy1v = iy - y0f;
        int y0 = (int)y0f, y1 = y0 + 1;
        float wy0 = (y0 >= 0 && y0 <= H - 1) ? (1.0f - wy1v) : 0.0f;
        float wy1 = (y1 >= 0 && y1 <= H - 1) ? wy1v : 0.0f;
        int y0c = min(max(y0, 0), H - 1);
        int y1c = min(max(y1, 0), H - 1);
        float yr = rintf(iy);
        int lyrow = (yr >= 0.0f && yr <= fh) ? ((int)yr) * W : -1;
        int ypack = y0c | (y1c << 9);
        syt[t] = make_float4(wy0, wy1, __int_as_float(ypack), __int_as_float(lyrow));
    }
    __syncthreads();

    const int rlo = blockIdx.y * ROWS_PER;
    const int rhi = min(rlo + ROWS_PER, CROP);
    const int npix = (rhi - rlo) * CROP;
    const int pixbase = rlo * CROP;

    const float* imgn  = img   + (size_t)n * 3 * plane;
    const int*   labn  = label + (size_t)n * plane;
    float*       outq  = out   + (size_t)q * 3 * PIX;
    float*       predq = out   + (size_t)N * 6 * 3 * PIX + (size_t)q * PIX;
    const int target = p + 1;

    for (int r = t; r < npix; r += 2 * THREADS) {
        // ---- pixel A = r ; pixel B = r + THREADS (clamped, stores predicated) ----
        int rB_raw = r + THREADS;
        bool hasB = rB_raw < npix;
        int rB = hasB ? rB_raw : r;

        int iA = (r  + pixbase) / CROP, jA = (r  + pixbase) % CROP;
        int iB = (rB + pixbase) / CROP, jB = (rB + pixbase) % CROP;

        // packed table reads: 4 x LDS.128
        float4 xa = sxt[jA], ya = syt[iA];
        float4 xb = sxt[jB], yb = syt[iB];

        int xpA = __float_as_int(xa.z), xpB = __float_as_int(xb.z);
        int ypA = __float_as_int(ya.z), ypB = __float_as_int(yb.z);

        int c0A = xpA & 511, c1A = (xpA >> 9) & 511, lxA = (xpA >> 18) - 1;
        int c0B = xpB & 511, c1B = (xpB >> 9) & 511, lxB = (xpB >> 18) - 1;
        int r0A = (ypA & 511) << 9, r1A = ((ypA >> 9) & 511) << 9;
        int r0B = (ypB & 511) << 9, r1B = ((ypB >> 9) & 511) << 9;
        int lyA = __float_as_int(ya.w), lyB = __float_as_int(yb.w);

        const float* p0A = imgn + r0A;
        const float* p1A = imgn + r1A;
        const float* p0B = imgn + r0B;
        const float* p1B = imgn + r1B;

        // ---- batched global loads: 24 img taps + 2 label taps in flight ----
        float v[24];
        #pragma unroll
        for (int c = 0; c < 3; ++c) {
            size_t cp = (size_t)c * plane;
            v[c*4+0]    = __ldg(p0A + cp + c0A);
            v[c*4+1]    = __ldg(p0A + cp + c1A);
            v[c*4+2]    = __ldg(p1A + cp + c0A);
            v[c*4+3]    = __ldg(p1A + cp + c1A);
            v[12+c*4+0] = __ldg(p0B + cp + c0B);
            v[12+c*4+1] = __ldg(p0B + cp + c1B);
            v[12+c*4+2] = __ldg(p1B + cp + c0B);
            v[12+c*4+3] = __ldg(p1B + cp + c1B);
        }
        int labA = ((lxA | lyA) >= 0) ? __ldg(labn + lyA + lxA) : 0;
        int labB = ((lxB | lyB) >= 0) ? __ldg(labn + lyB + lxB) : 0;

        // ---- compute & store ----
        float w00A = xa.x * ya.x, w10A = xa.y * ya.x, w01A = xa.x * ya.y, w11A = xa.y * ya.y;
        float w00B = xb.x * yb.x, w10B = xb.y * yb.x, w01B = xb.x * yb.y, w11B = xb.y * yb.y;
        int pixA = r + pixbase;
        int pixB = rB + pixbase;

        #pragma unroll
        for (int c = 0; c < 3; ++c) {
            outq[(size_t)c * PIX + pixA] =
                v[c*4+0]*w00A + v[c*4+1]*w10A + v[c*4+2]*w01A + v[c*4+3]*w11A;
        }
        float predA;
        if (p < 5) predA = (labA == target) ? 1.0f : 0.0f;
        else predA = (labA == 6) ? 1.0f : (labA == 7) ? 2.0f : (labA == 8) ? 3.0f : 0.0f;
        predq[pixA] = predA;

        if (hasB) {
            #pragma unroll
            for (int c = 0; c < 3; ++c) {
                outq[(size_t)c * PIX + pixB] =
                    v[12+c*4+0]*w00B + v[12+c*4+1]*w10B + v[12+c*4+2]*w01B + v[12+c*4+3]*w11B;
            }
            float predB;
            if (p < 5) predB = (labB == target) ? 1.0f : 0.0f;
            else predB = (labB == 6) ? 1.0f : (labB == 7) ? 2.0f : (labB == 8) ? 3.0f : 0.0f;
            predq[pixB] = predB;
        }
    }
}

extern "C" void kernel_launch(void* const* d_in, const int* in_sizes, int n_in,
                              void* d_out, int out_size) {
    const float* img    = (const float*)d_in[0];   // (N, 3, 512, 512) f32
    const int*   label  = (const int*)  d_in[1];   // (N, 512, 512) i32
    const float* points = (const float*)d_in[2];   // (N, 9, 2) f32
    float* out = (float*)d_out;

    int N = in_sizes[2] / 18;                      // points = N*9*2

    dim3 grid(N * 6, SPLIT);
    selectnet_kernel<<<grid, THREADS>>>(img, label, points, out, N);
}